// round 15
// baseline (speedup 1.0000x reference)
#include <cuda_runtime.h>
#include <cuda_bf16.h>

#define N_UNITS  8
#define M_ATOMS  1024
#define NPTS     (N_UNITS * M_ATOMS)

#define NBLK     444               // 148 SMs * 3 blocks — one perfectly balanced wave
#define THREADS  256
#define NPAIRS   28                // 8 choose 2
#define TOTCOL   (NPAIRS * M_ATOMS)   // 28672 pair-columns of work

typedef unsigned long long ull;

// Pre-scaled points: (sx, sy, sz, b) with s = sqrt(2*log2(e)) * p,
// b = log2(e) * (0.5 - |p|^2). log2(pen_ij) = b_i + b_j + s_i . s_j;
// row-sum factors as 2^{b_i} * sum_j 2^{b_j + s_i.s_j}.
__device__ float4 g_pts[NPTS];
__device__ int    g_cnt;           // monotonic barrier counter; replay-safe (launches serialize)

__device__ __forceinline__ float ex2f(float x) {
    float y;
    asm("ex2.approx.f32 %0, %1;" : "=f"(y) : "f"(x));
    return y;
}
__device__ __forceinline__ ull pack2(float a, float b) {
    ull d;
    asm("mov.b64 %0, {%1, %2};" : "=l"(d) : "f"(a), "f"(b));
    return d;
}
// 3x fma.rn.f32x2 dot (seeded with (w_j,w_j)) + 2x ex2, fused in one asm block
// so ptxas sees the whole dataflow and can alias the register pair.
__device__ __forceinline__ void dot_ex2(ull sx, ull sy, ull sz,
                                        ull xx, ull yy, ull zz, ull ww,
                                        float& e0, float& e1) {
    asm("{\n\t"
        ".reg .b64 t;\n\t"
        ".reg .f32 lo, hi;\n\t"
        "fma.rn.f32x2 t, %2, %3, %4;\n\t"
        "fma.rn.f32x2 t, %5, %6, t;\n\t"
        "fma.rn.f32x2 t, %7, %8, t;\n\t"
        "mov.b64 {lo, hi}, t;\n\t"
        "ex2.approx.f32 %0, lo;\n\t"
        "ex2.approx.f32 %1, hi;\n\t"
        "}"
        : "=f"(e0), "=f"(e1)
        : "l"(sx), "l"(xx), "l"(ww), "l"(sy), "l"(yy), "l"(sz), "l"(zz));
}

// ---------------------------------------------------------------------------
// ONE fused kernel: phase 1 (blocks 0..31) transforms the 8192 points and
// stages (s, b) in g_pts; device-wide barrier (all 444 CTAs resident by
// __launch_bounds__(256,3) -> no deadlock); phase 2 (all blocks) does the
// balanced pairwise sweep. All atomics to out happen post-barrier; out is
// zeroed pre-barrier by block 0 (release-fenced together with g_pts).
// ---------------------------------------------------------------------------
__global__ void __launch_bounds__(THREADS, 3)
fused_kernel(const float* __restrict__ positions,
             const float* __restrict__ euler,
             const float* __restrict__ coords,
             float* __restrict__ out)
{
    const float LOG2E = 1.4426950408889634f;
    const float CSC   = 1.69864122f;   // sqrt(2*LOG2E)

    int bid = blockIdx.x;
    int tid = threadIdx.x;
    int lane = tid & 31;
    int wid  = tid >> 5;

    __shared__ float sred[8];

    // ---------------- phase 1: transform (blocks 0..31) ----------------
    float l1part = 0.f;                 // held in a register across the barrier
    if (bid < 32) {
        int p = bid * THREADS + tid;    // 0..8191
        int n = p >> 10;
        int m = p & (M_ATOMS - 1);

        float sp, cp, st, ct, ss, cs;
        __sincosf(euler[n * 3 + 0], &sp, &cp);   // fast path; |angle|<~4, err << budget
        __sincosf(euler[n * 3 + 1], &st, &ct);
        __sincosf(euler[n * 3 + 2], &ss, &cs);

        float r00 = cs * ct;
        float r01 = cs * st * sp - ss * cp;
        float r02 = cs * st * cp + ss * sp;
        float r10 = ss * ct;
        float r11 = ss * st * sp + cs * cp;
        float r12 = ss * st * cp - cs * sp;
        float r20 = -st;
        float r21 = ct * sp;
        float r22 = ct * cp;

        float cx = coords[m * 3 + 0];
        float cy = coords[m * 3 + 1];
        float cz = coords[m * 3 + 2];

        float tx = fmaf(r00, cx, fmaf(r01, cy, fmaf(r02, cz, positions[n * 3 + 0])));
        float ty = fmaf(r10, cx, fmaf(r11, cy, fmaf(r12, cz, positions[n * 3 + 1])));
        float tz = fmaf(r20, cx, fmaf(r21, cy, fmaf(r22, cz, positions[n * 3 + 2])));

        float sq = fmaf(tx, tx, fmaf(ty, ty, tz * tz));

        float4 q;
        q.x = CSC * tx;
        q.y = CSC * ty;
        q.z = CSC * tz;
        q.w = fmaf(-LOG2E, sq, 0.5f * LOG2E);
        g_pts[p] = q;

        // block-reduce sum of squares (for L1 = total / N_UNITS)
        float v = sq;
        #pragma unroll
        for (int off = 16; off > 0; off >>= 1)
            v += __shfl_down_sync(0xffffffffu, v, off);
        if (lane == 0) sred[wid] = v;
        __syncthreads();
        if (tid == 0) {
            float t = 0.f;
            #pragma unroll
            for (int w = 0; w < 8; ++w) t += sred[w];
            l1part = t;
        }
    }
    if (bid == 0 && tid == 0) *out = 0.f;   // pre-barrier; all atomics are post-barrier

    // ---------------- device-wide barrier (monotonic counter) ----------------
    __syncthreads();                        // phase-1 writes + sred reuse safety
    if (tid == 0) {
        __threadfence();                    // release g_pts writes + out zero
        int t = atomicAdd(&g_cnt, 1) + 1;
        int target = ((t - 1) / NBLK + 1) * NBLK;
        while (atomicAdd(&g_cnt, 0) < target)
            __nanosleep(64);
        __threadfence();                    // acquire
    }
    __syncthreads();

    // post-barrier: transform-side contributions
    if (bid < 32 && tid == 0)
        atomicAdd(out, l1part * (1.0f / N_UNITS));
    if (bid == 0 && tid == 0) {
        float sx = 0.f, sy = 0.f, sz = 0.f;
        #pragma unroll
        for (int u = 0; u < N_UNITS; ++u) {
            sx += positions[u * 3 + 0];
            sy += positions[u * 3 + 1];
            sz += positions[u * 3 + 2];
        }
        atomicAdd(out, fmaf(sx, sx, fmaf(sy, sy, sz * sz)));   // ALPHA = 1
    }

    // ---------------- phase 2: balanced pairwise sweep ----------------
    // Global work = 28672 pair-columns (pair-major). 4-col units: blocks 0..63
    // take 17 units (68 cols), the rest 16 (64 cols) -> per-SM imbalance 1.2%.
    int u0 = (bid < 64) ? 17 * bid : 16 * bid + 64;
    int nu = (bid < 64) ? 17 : 16;
    int g  = 4 * u0;
    int g1 = g + 4 * nu;

    float stot = 0.f;
    while (g < g1) {
        int pr = g >> 10;                   // pair index 0..27
        // triangular decode -> (uu, vv), uu < vv   (<= 2 segments per block)
        int uu = 0, rem = pr;
        while (rem >= (N_UNITS - 1 - uu)) { rem -= (N_UNITS - 1 - uu); ++uu; }
        int vv = uu + 1 + rem;

        // i-rows of unit uu: 4 per thread, packed into f32x2 lanes
        const float4* pu = g_pts + uu * M_ATOMS + tid;
        float4 q0 = pu[0], q1 = pu[256], q2 = pu[512], q3 = pu[768];
        ull sx2[2], sy2[2], sz2[2];
        sx2[0] = pack2(q0.x, q1.x);  sx2[1] = pack2(q2.x, q3.x);
        sy2[0] = pack2(q0.y, q1.y);  sy2[1] = pack2(q2.y, q3.y);
        sz2[0] = pack2(q0.z, q1.z);  sz2[1] = pack2(q2.z, q3.z);
        float fi0 = ex2f(q0.w), fi1 = ex2f(q1.w);
        float fi2 = ex2f(q2.w), fi3 = ex2f(q3.w);
        float a0 = 0.f, a1 = 0.f, a2 = 0.f, a3 = 0.f;

        int gend = min(g1, (pr + 1) << 10); // end of this pair's segment
        const float4* pv = g_pts + vv * M_ATOMS + (g & (M_ATOMS - 1));
        int cnt = gend - g;

        #pragma unroll 4
        for (int c = 0; c < cnt; ++c) {
            float4 pj = pv[c];              // LDG.128 broadcast (L1/L2 resident)
            ull xx = pack2(pj.x, pj.x);
            ull yy = pack2(pj.y, pj.y);
            ull zz = pack2(pj.z, pj.z);
            ull ww = pack2(pj.w, pj.w);
            float e0, e1, e2, e3;
            dot_ex2(sx2[0], sy2[0], sz2[0], xx, yy, zz, ww, e0, e1);
            dot_ex2(sx2[1], sy2[1], sz2[1], xx, yy, zz, ww, e2, e3);
            a0 += e0; a1 += e1; a2 += e2; a3 += e3;
        }

        stot = fmaf(a0, fi0, stot);
        stot = fmaf(a1, fi1, stot);
        stot = fmaf(a2, fi2, stot);
        stot = fmaf(a3, fi3, stot);
        g = gend;
    }

    // block reduce + single atomic (LAMBDA1 = 0.5)
    #pragma unroll
    for (int off = 16; off > 0; off >>= 1)
        stot += __shfl_down_sync(0xffffffffu, stot, off);
    if (lane == 0) sred[wid] = stot;
    __syncthreads();
    if (tid == 0) {
        float t = 0.f;
        #pragma unroll
        for (int w = 0; w < 8; ++w) t += sred[w];
        atomicAdd(out, 0.5f * t);
    }
}

// ---------------------------------------------------------------------------
extern "C" void kernel_launch(void* const* d_in, const int* in_sizes, int n_in,
                              void* d_out, int out_size)
{
    const float* positions = (const float*)d_in[0];
    const float* euler     = (const float*)d_in[1];
    const float* coords    = (const float*)d_in[2];
    float*       out       = (float*)d_out;

    fused_kernel<<<NBLK, THREADS>>>(positions, euler, coords, out);
}